// round 13
// baseline (speedup 1.0000x reference)
#include <cuda_runtime.h>
#include <cstdint>

#define NPTS   34100
#define BATCHN 8
#define NGT    200
#define NLVL   5
#define NCAND  3500
#define MAXDET 300
#define IMGF   1280.0f
#define BIGF   2147483648.0f   // float32(2^31 - 1)
#define NWORDS 112             // bitmap words (110 used)
#define HALF   4               // images per stream pipeline
#define BROWS  3584            // band rows per image (NCAND padded to 256)

// output layout (float32, tuple flattened in return order)
#define OFF_MATCH  0
#define OFF_BOXES  272800
#define OFF_SCORES 282400
#define OFF_LABELS 284800
#define OFF_VALID  287200

// dynamic smem layout for scan_kernel (bytes)
#define SM_BOX   0              // float4[NCAND]            56000
#define SM_BAND  56000          // unsigned[2048]            8192
#define SM_S     64192          // unsigned[NWORDS]           448
#define SM_PICK  64640          // int[256]                  1024
#define SM_PAREA 65664          // float[256]                1024
#define SM_PBOX  66688          // float4[256]               4096
#define SCAN_SMEM 70784

__constant__ int c_loff[NLVL]  = {0, 25600, 32000, 33600, 34000};
__constant__ int c_lsize[NLVL] = {25600, 6400, 1600, 400, 100};
__constant__ int c_k[NLVL]     = {1000, 1000, 1000, 400, 100};
__constant__ int c_cbase[NLVL] = {0, 1000, 2000, 3000, 3400};

// scratch (static device globals; no allocation)
__device__ unsigned long long g_keys[BATCHN * NPTS];
__device__ unsigned long long g_ckey[BATCHN * NCAND];
__device__ float  g_cscore[BATCHN * NCAND];
__device__ float4 g_cbox[BATCHN * NCAND];
// sorted-by-key-desc candidate arrays
__device__ float4 g_sbox[BATCHN * NCAND];
__device__ float  g_sscore[BATCHN * NCAND];
__device__ float  g_sarea[BATCHN * NCAND];
__device__ int    g_nvalid[BATCHN];
// banded suppression: g_band[b][i][q] = row i's mask word at jw=(i>>5)+q, q<8
__device__ __align__(16) unsigned g_band[BATCHN * BROWS * 8];

// ---------------------------------------------------------------------------
// Stage 1: point -> gt box matching (argmin of area among containing boxes)
// ---------------------------------------------------------------------------
__global__ void match_kernel(const float* __restrict__ points,
                             const float* __restrict__ gt,
                             float* __restrict__ out, int b0) {
    const int b = b0 + blockIdx.y;
    __shared__ float4 sbox[NGT];
    __shared__ float  sar[NGT];
    for (int j = threadIdx.x; j < NGT; j += blockDim.x) {
        float4 g = ((const float4*)gt)[b * NGT + j];
        sbox[j] = g;
        sar[j] = (g.z - g.x) * (g.w - g.y);
    }
    __syncthreads();
    int p0 = (blockIdx.x * blockDim.x + threadIdx.x) * 4;   // NPTS % 4 == 0
    if (p0 >= NPTS) return;
    float4 q0 = ((const float4*)points)[(p0 >> 1) + 0];
    float4 q1 = ((const float4*)points)[(p0 >> 1) + 1];
    float px[4] = {q0.x, q0.z, q1.x, q1.z};
    float py[4] = {q0.y, q0.w, q1.y, q1.w};
    float best[4] = {BIGF, BIGF, BIGF, BIGF};
    int bi[4] = {0, 0, 0, 0};
    #pragma unroll 2
    for (int j = 0; j < NGT; ++j) {
        float4 g = sbox[j];
        float ar = sar[j];
        #pragma unroll
        for (int t = 0; t < 4; ++t) {
            bool in = (px[t] >= g.x) && (px[t] <= g.z) &&
                      (py[t] >= g.y) && (py[t] <= g.w);
            float c = in ? ar : BIGF;
            if (c < best[t]) { best[t] = c; bi[t] = j; }  // strict < == first-min
        }
    }
    float* o = out + OFF_MATCH + (size_t)b * NPTS + p0;
    #pragma unroll
    for (int t = 0; t < 4; ++t)
        o[t] = (float)(best[t] < BIGF ? bi[t] : -1);
}

// ---------------------------------------------------------------------------
// Stage 2: exact per-(image,level) top-k via 64-bit radix select on unique
// keys (ordered_score<<32 | ~local_idx); 256 bins, warp-aggregated atomics,
// early exit. Compaction: contiguous-chunk stable (2 barriers total).
// ---------------------------------------------------------------------------
__global__ void __launch_bounds__(1024)
topk_kernel(const float* __restrict__ cls,
            const float* __restrict__ reg,
            const float* __restrict__ points, int b0) {
    const int lvl = blockIdx.x;
    const int b = b0 + blockIdx.y;
    const int loff = c_loff[lvl], n = c_lsize[lvl], k = c_k[lvl];
    const int tid = threadIdx.x;
    const int lane = tid & 31, wid = tid >> 5;
    unsigned long long* keys = g_keys + (size_t)b * NPTS + loff;
    const float* logit = cls + (size_t)b * NPTS + loff;

    for (int i = tid; i < n; i += 1024) {
        float s = 1.0f / (1.0f + expf(-logit[i]));   // sigmoid
        unsigned int u = __float_as_uint(s);
        u = (u & 0x80000000u) ? ~u : (u | 0x80000000u);  // order-preserving
        keys[i] = ((unsigned long long)u << 32) |
                  (unsigned long long)(0xFFFFFFFFu - (unsigned)i);
    }
    __syncthreads();

    unsigned long long prefix = 0ULL;
    if (k < n) {
        __shared__ int hist[256];
        __shared__ unsigned long long s_pref;
        __shared__ int s_remk;
        __shared__ int s_done;
        int remk = k;
        const int iters = (n + 1023) >> 10;
        for (int pass = 0; pass < 8; ++pass) {
            const int shift = 56 - 8 * pass;
            const unsigned long long pmask =
                pass ? (~0ULL << (unsigned)(shift + 8)) : 0ULL;
            if (tid < 256) hist[tid] = 0;
            __syncthreads();
            for (int it = 0; it < iters; ++it) {
                int i = it * 1024 + tid;
                bool v = (i < n);
                unsigned long long kk = v ? keys[i] : 0ULL;
                int bin = (v && ((kk & pmask) == prefix))
                        ? (int)((kk >> shift) & 255) : 256;
                unsigned grp = __match_any_sync(0xFFFFFFFFu, bin);
                int leader = __ffs(grp) - 1;
                if (lane == leader && bin < 256)
                    atomicAdd(&hist[bin], __popc(grp));
            }
            __syncthreads();
            if (wid == 0) {
                int h[8];
                int t8 = 0;
                #pragma unroll
                for (int q = 0; q < 8; ++q) { h[q] = hist[lane * 8 + q]; t8 += h[q]; }
                int psum = t8;
                #pragma unroll
                for (int o = 1; o < 32; o <<= 1) {
                    int w = __shfl_down_sync(0xFFFFFFFFu, psum, o);
                    if (lane + o < 32) psum += w;
                }
                int above = psum - t8;
                if (above < remk && remk <= above + t8) {
                    int r = remk;
                    int c = above;
                    #pragma unroll
                    for (int q = 7; q >= 0; --q) {
                        if (r <= c + h[q]) {
                            s_pref = prefix | ((unsigned long long)(lane * 8 + q) << shift);
                            s_remk = r - c;
                            s_done = (r - c == h[q]) ? 1 : 0;
                            break;
                        }
                        c += h[q];
                    }
                }
            }
            __syncthreads();
            prefix = s_pref;
            remk = s_remk;
            if (s_done) break;
            __syncthreads();
        }
    }
    // exactly k keys satisfy key >= prefix

    // contiguous-chunk stable compaction (2 block barriers total)
    __shared__ int s_wincl[32];
    const int ce = (n + 1023) >> 10;        // elements per thread, contiguous
    const int start = tid * ce;
    int cnt = 0;
    for (int e = 0; e < ce; ++e) {
        int i = start + e;
        if (i < n && keys[i] >= prefix) cnt++;
    }
    int incl = cnt;
    #pragma unroll
    for (int o = 1; o < 32; o <<= 1) {
        int w = __shfl_up_sync(0xFFFFFFFFu, incl, o);
        if (lane >= o) incl += w;
    }
    if (lane == 31) s_wincl[wid] = incl;
    __syncthreads();
    if (wid == 0) {
        int v = s_wincl[lane];
        int sc = v;
        #pragma unroll
        for (int o = 1; o < 32; o <<= 1) {
            int w = __shfl_up_sync(0xFFFFFFFFu, sc, o);
            if (lane >= o) sc += w;
        }
        s_wincl[lane] = sc - v;   // exclusive over warps
    }
    __syncthreads();
    int pos = s_wincl[wid] + (incl - cnt);   // global stable rank base
    for (int e = 0; e < ce; ++e) {
        int i = start + e;
        if (i >= n) break;
        unsigned long long kk = keys[i];
        if (kk >= prefix) {
            int slot = c_cbase[lvl] + pos;
            pos++;
            int gidx = loff + i;
            unsigned int u = (unsigned int)(kk >> 32);
            unsigned int fb = (u & 0x80000000u) ? (u ^ 0x80000000u) : ~u;
            float score = __uint_as_float(fb);
            const float4 rg = ((const float4*)reg)[(size_t)b * NPTS + gidx];
            float2 p = ((const float2*)points)[gidx];
            float l = rg.x * IMGF, t = rg.y * IMGF;
            float r = rg.z * IMGF, bt = rg.w * IMGF;
            float x1 = fminf(fmaxf(p.x - l, 0.0f), IMGF);
            float y1 = fminf(fmaxf(p.y - t, 0.0f), IMGF);
            float x2 = fminf(fmaxf(p.x + r, 0.0f), IMGF);
            float y2 = fminf(fmaxf(p.y + bt, 0.0f), IMGF);
            int ci = b * NCAND + slot;
            g_cscore[ci] = score;
            g_cbox[ci] = make_float4(x1, y1, x2, y2);
            g_ckey[ci] = (score > 0.05f)
                       ? (((unsigned long long)u << 32) |
                          (unsigned long long)(0xFFFFFFFFu - (unsigned)slot))
                       : 0ULL;
        }
    }
}

// ---------------------------------------------------------------------------
// Stage 3a: per-image bitonic sort (desc) of candidate keys + gather.
// ---------------------------------------------------------------------------
__global__ void __launch_bounds__(1024)
sort_kernel(int b0) {
    const int b = b0 + blockIdx.x;
    const int tid = threadIdx.x;
    __shared__ unsigned long long sk[4096];
    for (int i = tid; i < 4096; i += 1024)
        sk[i] = (i < NCAND) ? g_ckey[b * NCAND + i] : 0ULL;
    __syncthreads();

    for (int k = 2; k <= 4096; k <<= 1) {
        for (int j = k >> 1; j > 0; j >>= 1) {
            for (int i = tid; i < 4096; i += 1024) {
                int ixj = i ^ j;
                if (ixj > i) {
                    bool up = ((i & k) == 0);
                    unsigned long long a = sk[i], c = sk[ixj];
                    if ((a > c) == up) { sk[i] = c; sk[ixj] = a; }
                }
            }
            int jnext = (j > 1) ? (j >> 1) : k;   // next k's first stage j == k
            if (j >= 32 || jnext >= 32) __syncthreads();
            else                        __syncwarp();
        }
    }

    __shared__ int s_nv;
    if (tid == 0) s_nv = 0;
    __syncthreads();
    int cnt = 0;
    for (int p = tid; p < NCAND; p += 1024) {
        unsigned long long key = sk[4095 - p];
        if (key) {
            cnt++;
            int slot = (int)(0xFFFFFFFFu - (unsigned)key);
            float4 bx = g_cbox[b * NCAND + slot];
            g_sbox[b * NCAND + p] = bx;
            g_sscore[b * NCAND + p] = g_cscore[b * NCAND + slot];
            g_sarea[b * NCAND + p] = (bx.z - bx.x) * (bx.w - bx.y);
        } else {
            g_sbox[b * NCAND + p] = make_float4(0.f, 0.f, 0.f, 0.f);
            g_sscore[b * NCAND + p] = 0.f;
            g_sarea[b * NCAND + p] = 0.f;
        }
    }
    cnt += __shfl_down_sync(0xFFFFFFFFu, cnt, 16);
    cnt += __shfl_down_sync(0xFFFFFFFFu, cnt, 8);
    cnt += __shfl_down_sync(0xFFFFFFFFu, cnt, 4);
    cnt += __shfl_down_sync(0xFFFFFFFFu, cnt, 2);
    cnt += __shfl_down_sync(0xFFFFFFFFu, cnt, 1);
    if ((tid & 31) == 0) atomicAdd(&s_nv, cnt);
    __syncthreads();
    if (tid == 0) g_nvalid[b] = s_nv;
}

// ---------------------------------------------------------------------------
// exact "fl(inter/denom) > 0.5" without division on the common path:
//   inter <= 0.5*denom            -> quotient <= 0.5          -> false
//   inter >  denom*0.5000002      -> quotient >  0.5 + 2^-25  -> true
//   else (~4e-7 relative band)    -> exact IEEE division
// ---------------------------------------------------------------------------
__device__ __forceinline__ bool iou_gt_half(float inter, float denom) {
    bool sup = inter > 0.5f * denom;
    if (sup && inter <= __fmul_rn(denom, 0.5000002f))
        sup = (inter / denom > 0.5f);
    return sup;
}

// ---------------------------------------------------------------------------
// Stage 3b: BAND-ONLY suppression bits: per row i, its 8 words covering
// jw in [i>>5, i>>5 + 8). One warp per pair of rows. ~7x less work than the
// full matrix; the scan recomputes beyond-band suppression on the fly.
// ---------------------------------------------------------------------------
__global__ void __launch_bounds__(256)
mask_kernel(int b0) {
    const int b = b0 + blockIdx.y;
    const int lane = threadIdx.x & 31;
    const int i0 = (blockIdx.x * 8 + (threadIdx.x >> 5)) * 2;
    const int nv = g_nvalid[b];
    if (i0 >= nv) return;
    const bool two = (i0 + 1 < nv);

    const float4 bA = g_sbox[b * NCAND + i0];
    const float  aA = g_sarea[b * NCAND + i0];
    const float4 bB = two ? g_sbox[b * NCAND + i0 + 1] : bA;
    const float  aB = two ? g_sarea[b * NCAND + i0 + 1] : aA;
    unsigned* bandA = g_band + ((size_t)b * BROWS + i0) * 8;
    unsigned* bandB = bandA + 8;

    const int iw = i0 >> 5;
    #pragma unroll
    for (int q = 0; q < 8; ++q) {
        const int j = (iw + q) * 32 + lane;
        float4 bj = make_float4(0.f, 0.f, 0.f, 0.f);
        float aj = 0.f;
        if (j < NCAND) {
            bj = g_sbox[b * NCAND + j];
            aj = g_sarea[b * NCAND + j];
        }
        bool supA = false;
        {
            float x1 = fmaxf(bA.x, bj.x), y1 = fmaxf(bA.y, bj.y);
            float x2 = fminf(bA.z, bj.z), y2 = fminf(bA.w, bj.w);
            float inter = fmaxf(x2 - x1, 0.0f) * fmaxf(y2 - y1, 0.0f);
            float denom = ((aA + aj) - inter) + 1e-9f;
            supA = (j > i0) && (j < NCAND) && iou_gt_half(inter, denom);
        }
        unsigned wA = __ballot_sync(0xFFFFFFFFu, supA);
        bool supB = false;
        {
            float x1 = fmaxf(bB.x, bj.x), y1 = fmaxf(bB.y, bj.y);
            float x2 = fminf(bB.z, bj.z), y2 = fminf(bB.w, bj.w);
            float inter = fmaxf(x2 - x1, 0.0f) * fmaxf(y2 - y1, 0.0f);
            float denom = ((aB + aj) - inter) + 1e-9f;
            supB = (j > i0 + 1) && (j < NCAND) && iou_gt_half(inter, denom);
        }
        unsigned wB = __ballot_sync(0xFFFFFFFFu, supB);
        if (lane == 0) {
            bandA[q] = wA;
            if (two) bandB[q] = wB;
        }
    }
}

// ---------------------------------------------------------------------------
// Stage 3c: fused scan, ONE 1024-thread block per image, all boxes in smem.
// Per 256-candidate super-word: load band slab (8KB), warp 0 resolves all
// picks serially from smem band + alive bitmap; then the WHOLE BLOCK
// suppresses future candidates by exact on-the-fly IoU vs the picked boxes
// (smem only). No full mask matrix, no global loads on the serial chain.
// ---------------------------------------------------------------------------
__global__ void __launch_bounds__(1024)
scan_kernel(float* __restrict__ out, int b0) {
    const int b = b0 + blockIdx.x;
    const int tid = threadIdx.x;
    const int lane = tid & 31, wrp = tid >> 5;
    extern __shared__ __align__(16) char dyn[];
    float4*   sbox  = (float4*)(dyn + SM_BOX);
    unsigned* sband = (unsigned*)(dyn + SM_BAND);
    unsigned* S     = (unsigned*)(dyn + SM_S);
    int*      spick = (int*)(dyn + SM_PICK);
    float*    sparea= (float*)(dyn + SM_PAREA);
    float4*   spbox = (float4*)(dyn + SM_PBOX);
    __shared__ int s_m;

    const int nvalid = g_nvalid[b];
    const int nw = (nvalid + 31) >> 5;
    const unsigned tailmask = (nvalid & 31) ? ((1u << (nvalid & 31)) - 1u)
                                            : 0xFFFFFFFFu;

    // preload all candidate boxes + zero bitmap
    for (int t = tid; t < NCAND; t += 1024)
        sbox[t] = g_sbox[b * NCAND + t];
    if (tid < NWORDS) S[tid] = 0u;

    int picks = 0;
    for (int w = 0; w < nw && picks < MAXDET; w += 8) {
        // load band slab for rows [w*32, w*32+256) : 512 uint4
        {
            const uint4* gb = (const uint4*)(g_band +
                              ((size_t)b * BROWS + (size_t)w * 32) * 8);
            if (tid < 512) ((uint4*)sband)[tid] = gb[tid];
        }
        __syncthreads();   // band + previous flush's S visible

        // warp 0: resolve all picks in this super-word (serial, smem only)
        if (wrp == 0) {
            unsigned A[8];
            #pragma unroll
            for (int kq = 0; kq < 8; ++kq) {
                int wk = w + kq;
                unsigned lm = (wk == nw - 1) ? tailmask : 0xFFFFFFFFu;
                A[kq] = (wk < nw) ? (~S[wk] & lm) : 0u;
            }
            int m = 0;
            int k = 0;
            while (k < 8 && picks + m < MAXDET) {
                unsigned bits = A[k];
                if (!bits) { k++; continue; }
                int bit = __ffs(bits) - 1;
                int il = k * 32 + bit;
                if (lane == 0) spick[m] = w * 32 + il;
                m++;
                #pragma unroll
                for (int q = 0; q < 8; ++q)
                    if (k + q < 8) A[k + q] &= ~sband[il * 8 + q];
                A[k] &= ~((2u << bit) - 1u);
            }
            __syncwarp();
            // fill pick boxes/areas (warp-parallel)
            for (int t = lane; t < m; t += 32) {
                float4 bx = sbox[spick[t]];
                spbox[t] = bx;
                sparea[t] = (bx.z - bx.x) * (bx.w - bx.y);
            }
            if (lane == 0) s_m = m;
        }
        __syncthreads();
        const int m = s_m;

        // outputs (block-parallel)
        for (int t = tid; t < m; t += 1024) {
            int i = spick[t];
            int oslot = b * MAXDET + picks + t;
            float4 bx = spbox[t];
            out[OFF_BOXES + (size_t)oslot * 4 + 0] = bx.x;
            out[OFF_BOXES + (size_t)oslot * 4 + 1] = bx.y;
            out[OFF_BOXES + (size_t)oslot * 4 + 2] = bx.z;
            out[OFF_BOXES + (size_t)oslot * 4 + 3] = bx.w;
            out[OFF_SCORES + oslot] = g_sscore[b * NCAND + i];
            out[OFF_LABELS + oslot] = 0.0f;
            out[OFF_VALID + oslot] = 1.0f;
        }
        picks += m;

        // flush: suppress future candidates (words >= w+8) by exact IoU
        if (m > 0 && picks < MAXDET && w + 8 < nw) {
            for (int jw = w + 8 + wrp; jw < nw; jw += 32) {
                unsigned cur = S[jw];
                int j = jw * 32 + lane;
                bool sup = false;
                if (j < nvalid && !((cur >> lane) & 1u)) {
                    float4 bj = sbox[j];
                    float aj = (bj.z - bj.x) * (bj.w - bj.y);
                    for (int t = 0; t < m && !sup; ++t) {
                        float4 bp = spbox[t];
                        float x1 = fmaxf(bp.x, bj.x), y1 = fmaxf(bp.y, bj.y);
                        float x2 = fminf(bp.z, bj.z), y2 = fminf(bp.w, bj.w);
                        float inter = fmaxf(x2 - x1, 0.0f) *
                                      fmaxf(y2 - y1, 0.0f);
                        float denom = ((sparea[t] + aj) - inter) + 1e-9f;
                        sup = iou_gt_half(inter, denom);
                    }
                }
                unsigned nb = __ballot_sync(0xFFFFFFFFu, sup);
                if (lane == 0) S[jw] = cur | nb;
            }
        }
        // no end barrier needed: next iteration's barrier orders S/sband
    }

    for (int jt = picks + tid; jt < MAXDET; jt += 1024) {
        int oslot = b * MAXDET + jt;
        out[OFF_BOXES + (size_t)oslot * 4 + 0] = 0.0f;
        out[OFF_BOXES + (size_t)oslot * 4 + 1] = 0.0f;
        out[OFF_BOXES + (size_t)oslot * 4 + 2] = 0.0f;
        out[OFF_BOXES + (size_t)oslot * 4 + 3] = 0.0f;
        out[OFF_SCORES + oslot] = 0.0f;
        out[OFF_LABELS + oslot] = -1.0f;
        out[OFF_VALID + oslot] = 0.0f;
    }
}

extern "C" void kernel_launch(void* const* d_in, const int* in_sizes, int n_in,
                              void* d_out, int out_size) {
    const float* points = (const float*)d_in[0];   // (34100, 2)
    const float* gt     = (const float*)d_in[1];   // (8, 200, 4)
    const float* cls    = (const float*)d_in[2];   // (8, 34100, 1)
    const float* reg    = (const float*)d_in[3];   // (8, 34100, 4)
    float* out = (float*)d_out;

    // ONE extra stream (proven 0-byte overhead); two half-batch pipelines.
    static cudaStream_t s2 = nullptr;
    static cudaEvent_t e_fork = nullptr, e_join = nullptr;
    if (s2 == nullptr) {
        cudaStreamCreateWithFlags(&s2, cudaStreamNonBlocking);
        cudaEventCreateWithFlags(&e_fork, cudaEventDisableTiming);
        cudaEventCreateWithFlags(&e_join, cudaEventDisableTiming);
        cudaFuncSetAttribute(scan_kernel,
            cudaFuncAttributeMaxDynamicSharedMemorySize, SCAN_SMEM);
    }

    cudaEventRecord(e_fork, 0);
    cudaStreamWaitEvent(s2, e_fork, 0);

    dim3 tg(NLVL, HALF);
    dim3 mk((NCAND / 2 + 7) / 8, HALF);
    dim3 mg((NPTS + 1023) / 1024, HALF);

    // pipeline A (capture stream): images 0-3
    topk_kernel<<<tg, 1024>>>(cls, reg, points, 0);
    sort_kernel<<<HALF, 1024>>>(0);
    mask_kernel<<<mk, 256>>>(0);
    scan_kernel<<<HALF, 1024, SCAN_SMEM>>>(out, 0);
    match_kernel<<<mg, 256>>>(points, gt, out, 0);

    // pipeline B (s2): images 4-7
    topk_kernel<<<tg, 1024, 0, s2>>>(cls, reg, points, HALF);
    sort_kernel<<<HALF, 1024, 0, s2>>>(HALF);
    mask_kernel<<<mk, 256, 0, s2>>>(HALF);
    scan_kernel<<<HALF, 1024, SCAN_SMEM, s2>>>(out, HALF);
    match_kernel<<<mg, 256, 0, s2>>>(points, gt, out, HALF);
    cudaEventRecord(e_join, s2);

    cudaStreamWaitEvent(0, e_join, 0);
}

// round 14
// speedup vs baseline: 1.5400x; 1.5400x over previous
#include <cuda_runtime.h>
#include <cstdint>

#define NPTS   34100
#define BATCHN 8
#define NGT    200
#define NLVL   5
#define NCAND  3500
#define MAXDET 300
#define IMGF   1280.0f
#define BIGF   2147483648.0f   // float32(2^31 - 1)
#define NWORDS 112             // row stride in words (110 used, uint4 aligned)
#define NCHUNK 28              // NWORDS/4
#define HALF   4               // images per stream pipeline
#define BROWS  3584            // band rows per image (NCAND padded to 256)

// output layout (float32, tuple flattened in return order)
#define OFF_MATCH  0
#define OFF_BOXES  272800
#define OFF_SCORES 282400
#define OFF_LABELS 284800
#define OFF_VALID  287200

__constant__ int c_loff[NLVL]  = {0, 25600, 32000, 33600, 34000};
__constant__ int c_lsize[NLVL] = {25600, 6400, 1600, 400, 100};
__constant__ int c_k[NLVL]     = {1000, 1000, 1000, 400, 100};
__constant__ int c_cbase[NLVL] = {0, 1000, 2000, 3000, 3400};

// scratch (static device globals; no allocation)
__device__ unsigned long long g_keys[BATCHN * NPTS];
__device__ unsigned long long g_ckey[BATCHN * NCAND];
__device__ float  g_cscore[BATCHN * NCAND];
__device__ float4 g_cbox[BATCHN * NCAND];
// sorted-by-key-desc candidate arrays
__device__ float4 g_sbox[BATCHN * NCAND];
__device__ float  g_sscore[BATCHN * NCAND];
__device__ float  g_sarea[BATCHN * NCAND];
__device__ int    g_nvalid[BATCHN];
// suppression bit matrix: row i -> bits over j (sorted order)
__device__ unsigned g_mask[BATCHN * NCAND * NWORDS];
// banded matrix: g_band[b][i][q] = row i's mask word at jw = (i>>5)+q, q<8
__device__ __align__(16) unsigned g_band[BATCHN * BROWS * 8];

// ---------------------------------------------------------------------------
// Stage 1: point -> gt box matching (argmin of area among containing boxes)
// ---------------------------------------------------------------------------
__global__ void match_kernel(const float* __restrict__ points,
                             const float* __restrict__ gt,
                             float* __restrict__ out, int b0) {
    const int b = b0 + blockIdx.y;
    __shared__ float4 sbox[NGT];
    __shared__ float  sar[NGT];
    for (int j = threadIdx.x; j < NGT; j += blockDim.x) {
        float4 g = ((const float4*)gt)[b * NGT + j];
        sbox[j] = g;
        sar[j] = (g.z - g.x) * (g.w - g.y);
    }
    __syncthreads();
    int p0 = (blockIdx.x * blockDim.x + threadIdx.x) * 4;   // NPTS % 4 == 0
    if (p0 >= NPTS) return;
    float4 q0 = ((const float4*)points)[(p0 >> 1) + 0];
    float4 q1 = ((const float4*)points)[(p0 >> 1) + 1];
    float px[4] = {q0.x, q0.z, q1.x, q1.z};
    float py[4] = {q0.y, q0.w, q1.y, q1.w};
    float best[4] = {BIGF, BIGF, BIGF, BIGF};
    int bi[4] = {0, 0, 0, 0};
    #pragma unroll 2
    for (int j = 0; j < NGT; ++j) {
        float4 g = sbox[j];
        float ar = sar[j];
        #pragma unroll
        for (int t = 0; t < 4; ++t) {
            bool in = (px[t] >= g.x) && (px[t] <= g.z) &&
                      (py[t] >= g.y) && (py[t] <= g.w);
            float c = in ? ar : BIGF;
            if (c < best[t]) { best[t] = c; bi[t] = j; }  // strict < == first-min
        }
    }
    float* o = out + OFF_MATCH + (size_t)b * NPTS + p0;
    #pragma unroll
    for (int t = 0; t < 4; ++t)
        o[t] = (float)(best[t] < BIGF ? bi[t] : -1);
}

// ---------------------------------------------------------------------------
// Stage 2: exact per-(image,level) top-k via 64-bit radix select on unique
// keys (ordered_score<<32 | ~local_idx); 256 bins, warp-aggregated atomics,
// early exit. Compaction: contiguous-chunk stable (2 barriers total).
// ---------------------------------------------------------------------------
__global__ void __launch_bounds__(1024)
topk_kernel(const float* __restrict__ cls,
            const float* __restrict__ reg,
            const float* __restrict__ points, int b0) {
    const int lvl = blockIdx.x;
    const int b = b0 + blockIdx.y;
    const int loff = c_loff[lvl], n = c_lsize[lvl], k = c_k[lvl];
    const int tid = threadIdx.x;
    const int lane = tid & 31, wid = tid >> 5;
    unsigned long long* keys = g_keys + (size_t)b * NPTS + loff;
    const float* logit = cls + (size_t)b * NPTS + loff;

    for (int i = tid; i < n; i += 1024) {
        float s = 1.0f / (1.0f + expf(-logit[i]));   // sigmoid
        unsigned int u = __float_as_uint(s);
        u = (u & 0x80000000u) ? ~u : (u | 0x80000000u);  // order-preserving
        keys[i] = ((unsigned long long)u << 32) |
                  (unsigned long long)(0xFFFFFFFFu - (unsigned)i);
    }
    __syncthreads();

    unsigned long long prefix = 0ULL;
    if (k < n) {
        __shared__ int hist[256];
        __shared__ unsigned long long s_pref;
        __shared__ int s_remk;
        __shared__ int s_done;
        int remk = k;
        const int iters = (n + 1023) >> 10;
        for (int pass = 0; pass < 8; ++pass) {
            const int shift = 56 - 8 * pass;
            const unsigned long long pmask =
                pass ? (~0ULL << (unsigned)(shift + 8)) : 0ULL;
            if (tid < 256) hist[tid] = 0;
            __syncthreads();
            for (int it = 0; it < iters; ++it) {
                int i = it * 1024 + tid;
                bool v = (i < n);
                unsigned long long kk = v ? keys[i] : 0ULL;
                int bin = (v && ((kk & pmask) == prefix))
                        ? (int)((kk >> shift) & 255) : 256;
                unsigned grp = __match_any_sync(0xFFFFFFFFu, bin);
                int leader = __ffs(grp) - 1;
                if (lane == leader && bin < 256)
                    atomicAdd(&hist[bin], __popc(grp));
            }
            __syncthreads();
            if (wid == 0) {
                int h[8];
                int t8 = 0;
                #pragma unroll
                for (int q = 0; q < 8; ++q) { h[q] = hist[lane * 8 + q]; t8 += h[q]; }
                int psum = t8;
                #pragma unroll
                for (int o = 1; o < 32; o <<= 1) {
                    int w = __shfl_down_sync(0xFFFFFFFFu, psum, o);
                    if (lane + o < 32) psum += w;
                }
                int above = psum - t8;
                if (above < remk && remk <= above + t8) {
                    int r = remk;
                    int c = above;
                    #pragma unroll
                    for (int q = 7; q >= 0; --q) {
                        if (r <= c + h[q]) {
                            s_pref = prefix | ((unsigned long long)(lane * 8 + q) << shift);
                            s_remk = r - c;
                            s_done = (r - c == h[q]) ? 1 : 0;
                            break;
                        }
                        c += h[q];
                    }
                }
            }
            __syncthreads();
            prefix = s_pref;
            remk = s_remk;
            if (s_done) break;
            __syncthreads();
        }
    }
    // exactly k keys satisfy key >= prefix

    // contiguous-chunk stable compaction (2 block barriers total)
    __shared__ int s_wincl[32];
    const int ce = (n + 1023) >> 10;        // elements per thread, contiguous
    const int start = tid * ce;
    int cnt = 0;
    for (int e = 0; e < ce; ++e) {
        int i = start + e;
        if (i < n && keys[i] >= prefix) cnt++;
    }
    int incl = cnt;
    #pragma unroll
    for (int o = 1; o < 32; o <<= 1) {
        int w = __shfl_up_sync(0xFFFFFFFFu, incl, o);
        if (lane >= o) incl += w;
    }
    if (lane == 31) s_wincl[wid] = incl;
    __syncthreads();
    if (wid == 0) {
        int v = s_wincl[lane];
        int sc = v;
        #pragma unroll
        for (int o = 1; o < 32; o <<= 1) {
            int w = __shfl_up_sync(0xFFFFFFFFu, sc, o);
            if (lane >= o) sc += w;
        }
        s_wincl[lane] = sc - v;   // exclusive over warps
    }
    __syncthreads();
    int pos = s_wincl[wid] + (incl - cnt);   // global stable rank base
    for (int e = 0; e < ce; ++e) {
        int i = start + e;
        if (i >= n) break;
        unsigned long long kk = keys[i];
        if (kk >= prefix) {
            int slot = c_cbase[lvl] + pos;
            pos++;
            int gidx = loff + i;
            unsigned int u = (unsigned int)(kk >> 32);
            unsigned int fb = (u & 0x80000000u) ? (u ^ 0x80000000u) : ~u;
            float score = __uint_as_float(fb);
            const float4 rg = ((const float4*)reg)[(size_t)b * NPTS + gidx];
            float2 p = ((const float2*)points)[gidx];
            float l = rg.x * IMGF, t = rg.y * IMGF;
            float r = rg.z * IMGF, bt = rg.w * IMGF;
            float x1 = fminf(fmaxf(p.x - l, 0.0f), IMGF);
            float y1 = fminf(fmaxf(p.y - t, 0.0f), IMGF);
            float x2 = fminf(fmaxf(p.x + r, 0.0f), IMGF);
            float y2 = fminf(fmaxf(p.y + bt, 0.0f), IMGF);
            int ci = b * NCAND + slot;
            g_cscore[ci] = score;
            g_cbox[ci] = make_float4(x1, y1, x2, y2);
            g_ckey[ci] = (score > 0.05f)
                       ? (((unsigned long long)u << 32) |
                          (unsigned long long)(0xFFFFFFFFu - (unsigned)slot))
                       : 0ULL;
        }
    }
}

// ---------------------------------------------------------------------------
// Stage 3a: per-image bitonic sort (desc) of candidate keys + gather.
// ---------------------------------------------------------------------------
__global__ void __launch_bounds__(1024)
sort_kernel(int b0) {
    const int b = b0 + blockIdx.x;
    const int tid = threadIdx.x;
    __shared__ unsigned long long sk[4096];
    for (int i = tid; i < 4096; i += 1024)
        sk[i] = (i < NCAND) ? g_ckey[b * NCAND + i] : 0ULL;
    __syncthreads();

    for (int k = 2; k <= 4096; k <<= 1) {
        for (int j = k >> 1; j > 0; j >>= 1) {
            for (int i = tid; i < 4096; i += 1024) {
                int ixj = i ^ j;
                if (ixj > i) {
                    bool up = ((i & k) == 0);
                    unsigned long long a = sk[i], c = sk[ixj];
                    if ((a > c) == up) { sk[i] = c; sk[ixj] = a; }
                }
            }
            int jnext = (j > 1) ? (j >> 1) : k;   // next k's first stage j == k
            if (j >= 32 || jnext >= 32) __syncthreads();
            else                        __syncwarp();
        }
    }

    __shared__ int s_nv;
    if (tid == 0) s_nv = 0;
    __syncthreads();
    int cnt = 0;
    for (int p = tid; p < NCAND; p += 1024) {
        unsigned long long key = sk[4095 - p];
        if (key) {
            cnt++;
            int slot = (int)(0xFFFFFFFFu - (unsigned)key);
            float4 bx = g_cbox[b * NCAND + slot];
            g_sbox[b * NCAND + p] = bx;
            g_sscore[b * NCAND + p] = g_cscore[b * NCAND + slot];
            g_sarea[b * NCAND + p] = (bx.z - bx.x) * (bx.w - bx.y);
        } else {
            g_sbox[b * NCAND + p] = make_float4(0.f, 0.f, 0.f, 0.f);
            g_sscore[b * NCAND + p] = 0.f;
            g_sarea[b * NCAND + p] = 0.f;
        }
    }
    cnt += __shfl_down_sync(0xFFFFFFFFu, cnt, 16);
    cnt += __shfl_down_sync(0xFFFFFFFFu, cnt, 8);
    cnt += __shfl_down_sync(0xFFFFFFFFu, cnt, 4);
    cnt += __shfl_down_sync(0xFFFFFFFFu, cnt, 2);
    cnt += __shfl_down_sync(0xFFFFFFFFu, cnt, 1);
    if ((tid & 31) == 0) atomicAdd(&s_nv, cnt);
    __syncthreads();
    if (tid == 0) g_nvalid[b] = s_nv;
}

// ---------------------------------------------------------------------------
// exact "fl(inter/denom) > 0.5" without division on the common path.
// ---------------------------------------------------------------------------
__device__ __forceinline__ bool iou_gt_half(float inter, float denom) {
    bool sup = inter > 0.5f * denom;
    if (sup && inter <= __fmul_rn(denom, 0.5000002f))
        sup = (inter / denom > 0.5f);
    return sup;
}

// ---------------------------------------------------------------------------
// Stage 3b: suppression bit matrix, one warp per PAIR of rows; additionally
// stores each row's first 8 words (the BAND) densely for the scan.
// ---------------------------------------------------------------------------
__global__ void __launch_bounds__(256)
mask_kernel(int b0) {
    const int b = b0 + blockIdx.y;
    const int lane = threadIdx.x & 31;
    const int i0 = (blockIdx.x * 8 + (threadIdx.x >> 5)) * 2;
    const int nv = g_nvalid[b];
    if (i0 >= nv) return;
    const bool two = (i0 + 1 < nv);

    const float4 bA = g_sbox[b * NCAND + i0];
    const float  aA = g_sarea[b * NCAND + i0];
    const float4 bB = two ? g_sbox[b * NCAND + i0 + 1] : bA;
    const float  aB = two ? g_sarea[b * NCAND + i0 + 1] : aA;
    unsigned* rowA = g_mask + ((size_t)(b * NCAND) + i0) * NWORDS;
    unsigned* rowB = rowA + NWORDS;
    unsigned* bandA = g_band + ((size_t)b * BROWS + i0) * 8;
    unsigned* bandB = bandA + 8;

    const int iw = i0 >> 5;
    const int jwmax = (nv + 31) >> 5;        // scan never reads words >= jwmax
    for (int jw = iw; jw < jwmax; ++jw) {
        const int j = jw * 32 + lane;
        float4 bj = make_float4(0.f, 0.f, 0.f, 0.f);
        float aj = 0.f;
        if (j < NCAND) {
            bj = g_sbox[b * NCAND + j];
            aj = g_sarea[b * NCAND + j];
        }
        bool supA = false;
        {
            float x1 = fmaxf(bA.x, bj.x), y1 = fmaxf(bA.y, bj.y);
            float x2 = fminf(bA.z, bj.z), y2 = fminf(bA.w, bj.w);
            float inter = fmaxf(x2 - x1, 0.0f) * fmaxf(y2 - y1, 0.0f);
            float denom = ((aA + aj) - inter) + 1e-9f;
            supA = (j > i0) && (j < NCAND) && iou_gt_half(inter, denom);
        }
        unsigned wA = __ballot_sync(0xFFFFFFFFu, supA);
        bool supB = false;
        {
            float x1 = fmaxf(bB.x, bj.x), y1 = fmaxf(bB.y, bj.y);
            float x2 = fminf(bB.z, bj.z), y2 = fminf(bB.w, bj.w);
            float inter = fmaxf(x2 - x1, 0.0f) * fmaxf(y2 - y1, 0.0f);
            float denom = ((aB + aj) - inter) + 1e-9f;
            supB = (j > i0 + 1) && (j < NCAND) && iou_gt_half(inter, denom);
        }
        unsigned wB = __ballot_sync(0xFFFFFFFFu, supB);
        if (lane == 0) {
            rowA[jw] = wA;
            if (jw - iw < 8) bandA[jw - iw] = wA;
            if (two) {
                rowB[jw] = wB;
                if (jw - iw < 8) bandB[jw - iw] = wB;
            }
        }
    }
}

// ---------------------------------------------------------------------------
// Stage 3c: SUPER-WORD (256-candidate) batched greedy scan (R12 design) with
// the resolve loop FULLY UNROLLED over k so the alive words A[0..7] live in
// REGISTERS (the R12 version's dynamic A[k+q] indexing spilled them to local
// memory, putting ~16 LDL/STL on every pick's serial chain). Also prefetches
// the next window's band slab (static address) at window start.
// ---------------------------------------------------------------------------
__global__ void __launch_bounds__(32)
scan_kernel(float* __restrict__ out, int b0) {
    const int b = b0 + blockIdx.x;
    const int lane = threadIdx.x;
    __shared__ __align__(16) unsigned sband[256 * 8];   // 8 KB

    const int nvalid = g_nvalid[b];
    const unsigned* mbase = g_mask + (size_t)b * NCAND * NWORDS;
    const int nw = (nvalid + 31) >> 5;
    const int nchunk = (nw + 3) >> 2;
    const unsigned tailmask = (nvalid & 31) ? ((1u << (nvalid & 31)) - 1u)
                                            : 0xFFFFFFFFu;

    uint4 Sreg = make_uint4(0u, 0u, 0u, 0u);  // lane c owns chunk c
    int picks = 0;

    for (int w = 0; w < nw && picks < MAXDET; w += 8) {
        // extract alive words for words w..w+7 (registers)
        unsigned A[8];
        #pragma unroll
        for (int kq = 0; kq < 8; ++kq) {
            int wk = w + kq;
            int c = wk & 3;
            unsigned comp = (c == 0) ? Sreg.x : (c == 1) ? Sreg.y
                          : (c == 2) ? Sreg.z : Sreg.w;
            unsigned sw = __shfl_sync(0xFFFFFFFFu, comp, wk >> 2);
            unsigned lm = (wk == nw - 1) ? tailmask : 0xFFFFFFFFu;
            A[kq] = (wk < nw) ? (~sw & lm) : 0u;
        }
        bool any = false;
        #pragma unroll
        for (int kq = 0; kq < 8; ++kq) any = any || (A[kq] != 0u);
        if (!any) continue;

        // load band slab for rows [w*32, w*32+256)
        {
            const uint4* gb = (const uint4*)(g_band +
                              ((size_t)b * BROWS + (size_t)w * 32) * 8);
            uint4* sb = (uint4*)sband;
            #pragma unroll
            for (int t = 0; t < 16; ++t)
                sb[t * 32 + lane] = gb[t * 32 + lane];
        }
        // prefetch next window's band slab (64 x 128B lines)
        if (w + 8 < nw) {
            const char* gn = (const char*)(g_band +
                             ((size_t)b * BROWS + (size_t)(w + 8) * 32) * 8);
            asm volatile("prefetch.global.L1 [%0];" :: "l"(gn + lane * 128));
            asm volatile("prefetch.global.L1 [%0];" :: "l"(gn + (lane + 32) * 128));
        }
        __syncwarp();

        const int cw = w >> 2;
        const bool doOR = (lane >= cw && lane < nchunk);
        const bool needS = (w + 8 < nw);   // future words exist
        int m = 0;
        int my_i = 0;

        // flush helper as macro (mutates m, picks, Sreg)
        #define FLUSH_M() do {                                               \
            if (lane < m) {                                                  \
                int oslot = b * MAXDET + picks + lane;                       \
                int ii = my_i;                                               \
                float4 bx = g_sbox[b * NCAND + ii];                          \
                out[OFF_BOXES + (size_t)oslot * 4 + 0] = bx.x;               \
                out[OFF_BOXES + (size_t)oslot * 4 + 1] = bx.y;               \
                out[OFF_BOXES + (size_t)oslot * 4 + 2] = bx.z;               \
                out[OFF_BOXES + (size_t)oslot * 4 + 3] = bx.w;               \
                out[OFF_SCORES + oslot] = g_sscore[b * NCAND + ii];          \
                out[OFF_LABELS + oslot] = 0.0f;                              \
                out[OFF_VALID + oslot] = 1.0f;                               \
            }                                                                \
            picks += m;                                                      \
            if (needS && picks < MAXDET) {                                   \
                for (int t = 0; t < m; ++t) {                                \
                    int i = __shfl_sync(0xFFFFFFFFu, my_i, t);               \
                    if (doOR) {                                              \
                        uint4 r = *((const uint4*)(mbase +                   \
                                    (size_t)i * NWORDS) + lane);             \
                        Sreg.x |= r.x; Sreg.y |= r.y;                        \
                        Sreg.z |= r.z; Sreg.w |= r.w;                        \
                    }                                                        \
                }                                                            \
            }                                                                \
            m = 0;                                                           \
        } while (0)

        // resolve: k fully unrolled -> A[] indices are compile-time constants
        #pragma unroll
        for (int k = 0; k < 8; ++k) {
            if (picks + m >= MAXDET) break;
            while (A[k]) {
                int bit = __ffs(A[k]) - 1;
                int il = k * 32 + bit;
                if (lane == m) my_i = w * 32 + il;
                m++;
                const unsigned* br = &sband[il * 8];
                #pragma unroll
                for (int q = k; q < 8; ++q)
                    A[q] &= ~br[q - k];
                A[k] &= ~((2u << bit) - 1u);
                if (m == 32) {
                    FLUSH_M();
                    if (picks >= MAXDET) break;
                }
                if (picks + m >= MAXDET) break;
            }
        }

        if (m > 0 && picks + m <= MAXDET + 32) FLUSH_M();
        #undef FLUSH_M
        __syncwarp();   // sband reuse next iteration
    }

    for (int jt = picks + lane; jt < MAXDET; jt += 32) {
        int oslot = b * MAXDET + jt;
        out[OFF_BOXES + (size_t)oslot * 4 + 0] = 0.0f;
        out[OFF_BOXES + (size_t)oslot * 4 + 1] = 0.0f;
        out[OFF_BOXES + (size_t)oslot * 4 + 2] = 0.0f;
        out[OFF_BOXES + (size_t)oslot * 4 + 3] = 0.0f;
        out[OFF_SCORES + oslot] = 0.0f;
        out[OFF_LABELS + oslot] = -1.0f;
        out[OFF_VALID + oslot] = 0.0f;
    }
}

extern "C" void kernel_launch(void* const* d_in, const int* in_sizes, int n_in,
                              void* d_out, int out_size) {
    const float* points = (const float*)d_in[0];   // (34100, 2)
    const float* gt     = (const float*)d_in[1];   // (8, 200, 4)
    const float* cls    = (const float*)d_in[2];   // (8, 34100, 1)
    const float* reg    = (const float*)d_in[3];   // (8, 34100, 4)
    float* out = (float*)d_out;

    // ONE extra stream (proven 0-byte overhead); two half-batch pipelines.
    static cudaStream_t s2 = nullptr;
    static cudaEvent_t e_fork = nullptr, e_join = nullptr;
    if (s2 == nullptr) {
        cudaStreamCreateWithFlags(&s2, cudaStreamNonBlocking);
        cudaEventCreateWithFlags(&e_fork, cudaEventDisableTiming);
        cudaEventCreateWithFlags(&e_join, cudaEventDisableTiming);
    }

    cudaEventRecord(e_fork, 0);
    cudaStreamWaitEvent(s2, e_fork, 0);

    const int maskblocks = (NCAND / 2 + 7) / 8;
    dim3 tg(NLVL, HALF);
    dim3 mk(maskblocks, HALF);
    dim3 mg((NPTS + 1023) / 1024, HALF);

    // pipeline A (capture stream): images 0-3
    topk_kernel<<<tg, 1024>>>(cls, reg, points, 0);
    sort_kernel<<<HALF, 1024>>>(0);
    mask_kernel<<<mk, 256>>>(0);
    scan_kernel<<<HALF, 32>>>(out, 0);
    match_kernel<<<mg, 256>>>(points, gt, out, 0);

    // pipeline B (s2): images 4-7
    topk_kernel<<<tg, 1024, 0, s2>>>(cls, reg, points, HALF);
    sort_kernel<<<HALF, 1024, 0, s2>>>(HALF);
    mask_kernel<<<mk, 256, 0, s2>>>(HALF);
    scan_kernel<<<HALF, 32, 0, s2>>>(out, HALF);
    match_kernel<<<mg, 256, 0, s2>>>(points, gt, out, HALF);
    cudaEventRecord(e_join, s2);

    cudaStreamWaitEvent(0, e_join, 0);
}